// round 12
// baseline (speedup 1.0000x reference)
#include <cuda_runtime.h>
#include <cuda_fp16.h>
#include <math.h>
#include <stdint.h>

#define BB 16
#define TT 2048
#define DD 1024
#define MROWS (BB * TT)       // 32768
#define LN_EPS 1e-5f

// ---- GEMM tiling (R10 proven shape) ----
#define BM 128
#define BN 128
#define BK 64                  // fp16 elems per k-chunk (4 kk-steps of 16)
#define NSTAGE 2
#define NTHREADS 256
#define ROWB 144               // 128B data + 16B pad (conflict-free ldmatrix)
#define A_HI_OFF 0
#define A_LO_OFF (BM * ROWB)                     // 18432
#define B_HI_OFF (2 * BM * ROWB)                 // 36864
#define STAGE_B  (2 * BM * ROWB + BN * ROWB)     // 55296
#define SMEM_TOTAL (NSTAGE * STAGE_B)            // 110592 -> 2 CTAs/SM
#define GROUP_M 16

// ---- scratch (__device__ globals; no cudaMalloc allowed) ----
__device__ __half g_xhi[(size_t)MROWS * DD];
__device__ __half g_xlo[(size_t)MROWS * DD];
__device__ __half g_wh [(size_t)2 * DD * DD];    // W_in fp16
__device__ __half g_sh [(size_t)DD * DD];        // W_state fp16
__device__ __half g_vhi[(size_t)MROWS * DD];     // vx fp16
__device__ __half g_ch [(size_t)MROWS * DD];     // cand fp16
__device__ __half g_y  [(size_t)MROWS * DD];     // y fp16
__device__ float g_u[(size_t)MROWS * DD];

// ============================ device helpers ============================
__device__ __forceinline__ uint32_t smem_u32(const void* p) {
    uint32_t a;
    asm("{ .reg .u64 t; cvta.to.shared.u64 t, %1; cvt.u32.u64 %0, t; }" : "=r"(a) : "l"(p));
    return a;
}
__device__ __forceinline__ void cp16(uint32_t dst, const void* src) {
    asm volatile("cp.async.cg.shared.global [%0], [%1], 16;" :: "r"(dst), "l"(src));
}
__device__ __forceinline__ void cp_commit() {
    asm volatile("cp.async.commit_group;" ::: "memory");
}
template <int N>
__device__ __forceinline__ void cp_wait() {
    asm volatile("cp.async.wait_group %0;" :: "n"(N) : "memory");
}
__device__ __forceinline__ void ldsm4(uint32_t* r, uint32_t a) {
    asm volatile("ldmatrix.sync.aligned.m8n8.x4.shared.b16 {%0,%1,%2,%3}, [%4];"
                 : "=r"(r[0]), "=r"(r[1]), "=r"(r[2]), "=r"(r[3]) : "r"(a));
}
__device__ __forceinline__ void mma16816(float* c, const uint32_t* a, const uint32_t* b) {
    asm volatile(
        "mma.sync.aligned.m16n8k16.row.col.f32.f16.f16.f32 "
        "{%0,%1,%2,%3},{%4,%5,%6,%7},{%8,%9},{%0,%1,%2,%3};"
        : "+f"(c[0]), "+f"(c[1]), "+f"(c[2]), "+f"(c[3])
        : "r"(a[0]), "r"(a[1]), "r"(a[2]), "r"(a[3]), "r"(b[0]), "r"(b[1]));
}

// ============================ conversions ============================
__global__ __launch_bounds__(256) void split_kernel(
    const float* __restrict__ src, __half* __restrict__ hi,
    __half* __restrict__ lo, int n)
{
    int i = (blockIdx.x * blockDim.x + threadIdx.x) * 4;
    if (i < n) {
        float4 v = *(const float4*)(src + i);
        float vv[4] = {v.x, v.y, v.z, v.w};
        unsigned short hb[4], lb[4];
#pragma unroll
        for (int e = 0; e < 4; e++) {
            __half h = __float2half_rn(vv[e]);
            float r = vv[e] - __half2float(h);
            hb[e] = __half_as_ushort(h);
            lb[e] = __half_as_ushort(__float2half_rn(r));
        }
        *(uint2*)(hi + i) = make_uint2((uint32_t)hb[0] | ((uint32_t)hb[1] << 16),
                                       (uint32_t)hb[2] | ((uint32_t)hb[3] << 16));
        *(uint2*)(lo + i) = make_uint2((uint32_t)lb[0] | ((uint32_t)lb[1] << 16),
                                       (uint32_t)lb[2] | ((uint32_t)lb[3] << 16));
    }
}

__global__ __launch_bounds__(256) void conv_kernel(
    const float* __restrict__ src, __half* __restrict__ dst, int n)
{
    int i = (blockIdx.x * blockDim.x + threadIdx.x) * 4;
    if (i < n) {
        float4 v = *(const float4*)(src + i);
        unsigned short hb[4];
        hb[0] = __half_as_ushort(__float2half_rn(v.x));
        hb[1] = __half_as_ushort(__float2half_rn(v.y));
        hb[2] = __half_as_ushort(__float2half_rn(v.z));
        hb[3] = __half_as_ushort(__float2half_rn(v.w));
        *(uint2*)(dst + i) = make_uint2((uint32_t)hb[0] | ((uint32_t)hb[1] << 16),
                                        (uint32_t)hb[2] | ((uint32_t)hb[3] << 16));
    }
}

// ============================ fp16 mma.sync GEMM ============================
// C[BM,BN] tile of A @ B^T.  A:[M,K] fp16 (hi[,lo]) row-major, B:[N,K] fp16 row-major.
// SPLIT_A=1: acc = Ahi@B^T + Alo@B^T ;  SPLIT_A=0: acc = A@B^T.
// 256 threads: 8 warps = 4 m-slices (32) x 2 n-slices (64). 2 CTAs/SM.
// MODE 0: outF = sigmoid(acc) fp32   (gate half of GEMM1 -> u)
// MODE 1: outH = fp16(acc)           (value half of GEMM1 -> vx; GEMM2 -> cand)
template <int MODE, int SPLIT_A>
__global__ __launch_bounds__(NTHREADS, 2)
void gemm_mma(const __half* __restrict__ Ahi, const __half* __restrict__ Alo,
              const __half* __restrict__ Bh,
              float* __restrict__ outF,
              __half* __restrict__ outH,
              int ntn)
{
    extern __shared__ char smem[];
    const uint32_t sb = smem_u32(smem);
    const int tid = threadIdx.x;
    const int wid = tid >> 5, lane = tid & 31;

    int per_group = GROUP_M * ntn;
    int group = blockIdx.x / per_group;
    int rem = blockIdx.x % per_group;
    const int bm = (group * GROUP_M + (rem % GROUP_M)) * BM;
    const int bn = (rem / GROUP_M) * BN;

    const int wm = wid & 3;   // 4 m-slices of 32
    const int wn = wid >> 2;  // 2 n-slices of 64

    uint32_t offA[2], offB[4];
#pragma unroll
    for (int mf = 0; mf < 2; mf++)
        offA[mf] = (uint32_t)(wm * 32 + mf * 16 + (lane & 15)) * ROWB + (lane >> 4) * 16;
#pragma unroll
    for (int p = 0; p < 4; p++)
        offB[p] = (uint32_t)(wn * 64 + p * 16 + ((lane >> 4) & 1) * 8 + (lane & 7)) * ROWB
                  + ((lane >> 3) & 1) * 16;

    float acc[2][8][4];
#pragma unroll
    for (int a = 0; a < 2; a++)
#pragma unroll
        for (int b = 0; b < 8; b++)
#pragma unroll
            for (int e = 0; e < 4; e++) acc[a][b][e] = 0.f;

    auto load_half = [&](int kc, int half) {
        uint32_t base = sb + (uint32_t)(kc % NSTAGE) * STAGE_B;
        int k0 = kc * BK;
#pragma unroll
        for (int j = 0; j < 2; j++) {
            int ch = tid + (half * 2 + j) * NTHREADS;   // [0, 1024)
            int row = ch >> 3, kc8 = ch & 7;
            uint32_t doff = (uint32_t)row * ROWB + kc8 * 16;
            size_t ga = (size_t)(bm + row) * DD + k0 + kc8 * 8;
            cp16(base + A_HI_OFF + doff, Ahi + ga);
            if (SPLIT_A) cp16(base + A_LO_OFF + doff, Alo + ga);
            size_t gb = (size_t)(bn + row) * DD + k0 + kc8 * 8;
            cp16(base + B_HI_OFF + doff, Bh + gb);
        }
    };

    load_half(0, 0);
    load_half(0, 1);
    cp_commit();

    const int NKC = DD / BK;   // 16
    for (int kc = 0; kc < NKC; kc++) {
        cp_wait<0>();
        __syncthreads();

        uint32_t base = sb + (uint32_t)(kc % NSTAGE) * STAGE_B;
#pragma unroll
        for (int kk = 0; kk < 4; kk++) {
            uint32_t ah[2][4], al[2][4], bh[4][4];
#pragma unroll
            for (int mf = 0; mf < 2; mf++) {
                ldsm4(ah[mf], base + A_HI_OFF + offA[mf] + kk * 32);
                if (SPLIT_A) ldsm4(al[mf], base + A_LO_OFF + offA[mf] + kk * 32);
            }
#pragma unroll
            for (int p = 0; p < 4; p++)
                ldsm4(bh[p], base + B_HI_OFF + offB[p] + kk * 32);
            if (kc + 1 < NKC) {
                if (kk == 0) load_half(kc + 1, 0);
                if (kk == 1) { load_half(kc + 1, 1); cp_commit(); }
            }
#pragma unroll
            for (int mf = 0; mf < 2; mf++) {
#pragma unroll
                for (int nf = 0; nf < 8; nf++) {
                    const uint32_t* b2 = &bh[nf >> 1][(nf & 1) * 2];
                    mma16816(acc[mf][nf], ah[mf], b2);
                    if (SPLIT_A) mma16816(acc[mf][nf], al[mf], b2);
                }
            }
        }
    }

    // ---- epilogue ----
    const int r0 = bm + wm * 32 + (lane >> 2);
    const int c0 = bn + wn * 64 + (lane & 3) * 2;

#pragma unroll
    for (int mf = 0; mf < 2; mf++) {
        int r = r0 + mf * 16;
#pragma unroll
        for (int nf = 0; nf < 8; nf++) {
            int c = c0 + nf * 8;
            float* a = acc[mf][nf];
            if (MODE == 0) {
                float2 s0, s1;
                s0.x = 1.f / (1.f + __expf(-a[0]));
                s0.y = 1.f / (1.f + __expf(-a[1]));
                s1.x = 1.f / (1.f + __expf(-a[2]));
                s1.y = 1.f / (1.f + __expf(-a[3]));
                *(float2*)(outF + (size_t)r * DD + c)       = s0;
                *(float2*)(outF + (size_t)(r + 8) * DD + c) = s1;
            } else {
                __half2 h0 = __floats2half2_rn(a[0], a[1]);
                __half2 h1 = __floats2half2_rn(a[2], a[3]);
                *(__half2*)(outH + (size_t)r * DD + c)       = h0;
                *(__half2*)(outH + (size_t)(r + 8) * DD + c) = h1;
            }
        }
    }
}

// ============================ scan (diagonal recurrence) ============================
// h_t = u*h + (1-u)*c. Reads g_u (fp32) + g_ch (fp16); writes g_y (fp16).
__global__ __launch_bounds__(256) void scan_kernel()
{
    int idx = blockIdx.x * blockDim.x + threadIdx.x;
    int b = idx >> 10;
    int d = idx & (DD - 1);
    const float* up = g_u + (size_t)b * TT * DD + d;
    const __half* cp = g_ch + (size_t)b * TT * DD + d;
    __half* yp = g_y + (size_t)b * TT * DD + d;
    float h = 0.f;
    for (int t = 0; t < TT; t += 16) {
        float uu[16], cc[16];
#pragma unroll
        for (int j = 0; j < 16; j++) {
            uu[j] = up[(size_t)(t + j) * DD];
            cc[j] = __half2float(cp[(size_t)(t + j) * DD]);
        }
#pragma unroll
        for (int j = 0; j < 16; j++) {
            h = fmaf(uu[j], h - cc[j], cc[j]);
            cc[j] = h;
        }
#pragma unroll
        for (int j = 0; j < 16; j++) yp[(size_t)(t + j) * DD] = __float2half_rn(cc[j]);
    }
}

// ============================ LayerNorm ============================
__global__ __launch_bounds__(256) void ln_kernel(const float* __restrict__ gamma,
                                                 const float* __restrict__ beta,
                                                 float* __restrict__ out)
{
    int row = blockIdx.x;
    int t = threadIdx.x;
    const __half2* yr = (const __half2*)(g_y + (size_t)row * DD);
    __half2 p0 = yr[t * 2], p1 = yr[t * 2 + 1];
    float2 f0 = __half22float2(p0), f1 = __half22float2(p1);
    float s = f0.x + f0.y + f1.x + f1.y;
    float q = f0.x * f0.x + f0.y * f0.y + f1.x * f1.x + f1.y * f1.y;

#pragma unroll
    for (int o = 16; o; o >>= 1) {
        s += __shfl_xor_sync(0xFFFFFFFFu, s, o);
        q += __shfl_xor_sync(0xFFFFFFFFu, q, o);
    }
    __shared__ float sw[8], qw[8];
    __shared__ float mu_s, inv_s;
    int w = t >> 5, l = t & 31;
    if (l == 0) { sw[w] = s; qw[w] = q; }
    __syncthreads();
    if (t == 0) {
        float S = 0.f, Q = 0.f;
#pragma unroll
        for (int i = 0; i < 8; i++) { S += sw[i]; Q += qw[i]; }
        float mu = S * (1.f / DD);
        float var = Q * (1.f / DD) - mu * mu;
        mu_s = mu;
        inv_s = rsqrtf(var + LN_EPS);
    }
    __syncthreads();
    float mu = mu_s, inv = inv_s;

    const float4* g4 = (const float4*)gamma;
    const float4* b4 = (const float4*)beta;
    float4 gv = g4[t], bv = b4[t];
    float4 o;
    o.x = (f0.x - mu) * inv * gv.x + bv.x;
    o.y = (f0.y - mu) * inv * gv.y + bv.y;
    o.z = (f1.x - mu) * inv * gv.z + bv.z;
    o.w = (f1.y - mu) * inv * gv.w + bv.w;
    ((float4*)(out + (size_t)row * DD))[t] = o;
}

// ============================ host ============================
extern "C" void kernel_launch(void* const* d_in, const int* in_sizes, int n_in,
                              void* d_out, int out_size)
{
    const float* x       = (const float*)d_in[0];
    const float* W_in    = (const float*)d_in[1];
    const float* W_state = (const float*)d_in[2];
    const float* gamma   = (const float*)d_in[3];
    const float* beta    = (const float*)d_in[4];
    float* out = (float*)d_out;

    void *pxh, *pxl, *pwh, *psh, *pvh, *pch, *pu;
    cudaGetSymbolAddress(&pxh, g_xhi); cudaGetSymbolAddress(&pxl, g_xlo);
    cudaGetSymbolAddress(&pwh, g_wh);  cudaGetSymbolAddress(&psh, g_sh);
    cudaGetSymbolAddress(&pvh, g_vhi); cudaGetSymbolAddress(&pch, g_ch);
    cudaGetSymbolAddress(&pu,  g_u);

    cudaFuncSetAttribute((const void*)gemm_mma<0, 0>, cudaFuncAttributeMaxDynamicSharedMemorySize, SMEM_TOTAL);
    cudaFuncSetAttribute((const void*)gemm_mma<1, 1>, cudaFuncAttributeMaxDynamicSharedMemorySize, SMEM_TOTAL);
    cudaFuncSetAttribute((const void*)gemm_mma<1, 0>, cudaFuncAttributeMaxDynamicSharedMemorySize, SMEM_TOTAL);

    // conversions
    { int n = MROWS * DD;  split_kernel<<<(n / 4 + 255) / 256, 256>>>(x, (__half*)pxh, (__half*)pxl, n); }
    { int n = 2 * DD * DD; conv_kernel<<<(n / 4 + 255) / 256, 256>>>(W_in, (__half*)pwh, n); }
    { int n = DD * DD;     conv_kernel<<<(n / 4 + 255) / 256, 256>>>(W_state, (__half*)psh, n); }

    const int ntm = MROWS / BM;        // 256
    const int ntn = DD / BN;           // 8

    // GEMM1 gate half: x @ W_in[0:D]^T -> u = sigmoid (fp32)
    gemm_mma<0, 0><<<ntm * ntn, NTHREADS, SMEM_TOTAL>>>(
        (const __half*)pxh, nullptr, (const __half*)pwh,
        (float*)pu, nullptr, ntn);

    // GEMM1 value half: (x_hi + x_lo) @ W_in[D:2D]^T -> vx fp16
    gemm_mma<1, 1><<<ntm * ntn, NTHREADS, SMEM_TOTAL>>>(
        (const __half*)pxh, (const __half*)pxl, (const __half*)pwh + (size_t)DD * DD,
        nullptr, (__half*)pvh, ntn);

    // GEMM2: vx @ W_state^T -> cand fp16
    gemm_mma<1, 0><<<ntm * ntn, NTHREADS, SMEM_TOTAL>>>(
        (const __half*)pvh, nullptr, (const __half*)psh,
        nullptr, (__half*)pch, ntn);

    // scan over T -> y fp16, then LN -> out fp32
    scan_kernel<<<(BB * DD) / 256, 256>>>();
    ln_kernel<<<MROWS, 256>>>(gamma, beta, out);
}

// round 13
// speedup vs baseline: 1.2035x; 1.2035x over previous
#include <cuda_runtime.h>
#include <cuda_fp16.h>
#include <math.h>
#include <stdint.h>

#define BB 16
#define TT 2048
#define DD 1024
#define MROWS (BB * TT)       // 32768
#define LN_EPS 1e-5f

// ---- GEMM tiling (proven R10 shape) ----
#define BM 128
#define BN 128
#define BK 64                  // fp16 elems per k-chunk (4 kk-steps of 16)
#define NSTAGE 2
#define NTHREADS 256
#define ROWB 144               // 128B data + 16B pad (conflict-free ldmatrix)
#define A_OFF 0
#define B_OFF (BM * ROWB)                        // 18432
#define STAGE_B  (BM * ROWB + BN * ROWB)         // 36864
#define SMEM_TOTAL (NSTAGE * STAGE_B)            // 73728 -> 2 CTAs/SM (reg-limited)
#define GROUP_M 16

// ---- scratch (__device__ globals; no cudaMalloc allowed) ----
__device__ __half g_xh [(size_t)MROWS * DD];     // x fp16
__device__ __half g_wh [(size_t)2 * DD * DD];    // W_in fp16
__device__ __half g_sh [(size_t)DD * DD];        // W_state fp16
__device__ __half g_vh [(size_t)MROWS * DD];     // vx fp16
__device__ float g_u[(size_t)MROWS * DD];        // u fp32
__device__ float g_c[(size_t)MROWS * DD];        // cand fp32; scan writes y in place

// ============================ device helpers ============================
__device__ __forceinline__ uint32_t smem_u32(const void* p) {
    uint32_t a;
    asm("{ .reg .u64 t; cvta.to.shared.u64 t, %1; cvt.u32.u64 %0, t; }" : "=r"(a) : "l"(p));
    return a;
}
__device__ __forceinline__ void cp16(uint32_t dst, const void* src) {
    asm volatile("cp.async.cg.shared.global [%0], [%1], 16;" :: "r"(dst), "l"(src));
}
__device__ __forceinline__ void cp_commit() {
    asm volatile("cp.async.commit_group;" ::: "memory");
}
template <int N>
__device__ __forceinline__ void cp_wait() {
    asm volatile("cp.async.wait_group %0;" :: "n"(N) : "memory");
}
__device__ __forceinline__ void ldsm4(uint32_t* r, uint32_t a) {
    asm volatile("ldmatrix.sync.aligned.m8n8.x4.shared.b16 {%0,%1,%2,%3}, [%4];"
                 : "=r"(r[0]), "=r"(r[1]), "=r"(r[2]), "=r"(r[3]) : "r"(a));
}
__device__ __forceinline__ void mma16816(float* c, const uint32_t* a, const uint32_t* b) {
    asm volatile(
        "mma.sync.aligned.m16n8k16.row.col.f32.f16.f16.f32 "
        "{%0,%1,%2,%3},{%4,%5,%6,%7},{%8,%9},{%0,%1,%2,%3};"
        : "+f"(c[0]), "+f"(c[1]), "+f"(c[2]), "+f"(c[3])
        : "r"(a[0]), "r"(a[1]), "r"(a[2]), "r"(a[3]), "r"(b[0]), "r"(b[1]));
}

// ============================ conversions ============================
// fp32 -> fp16
__global__ __launch_bounds__(256) void conv_kernel(
    const float* __restrict__ src, __half* __restrict__ dst, int n)
{
    int i = (blockIdx.x * blockDim.x + threadIdx.x) * 4;
    if (i < n) {
        float4 v = *(const float4*)(src + i);
        unsigned short hb[4];
        hb[0] = __half_as_ushort(__float2half_rn(v.x));
        hb[1] = __half_as_ushort(__float2half_rn(v.y));
        hb[2] = __half_as_ushort(__float2half_rn(v.z));
        hb[3] = __half_as_ushort(__float2half_rn(v.w));
        *(uint2*)(dst + i) = make_uint2((uint32_t)hb[0] | ((uint32_t)hb[1] << 16),
                                        (uint32_t)hb[2] | ((uint32_t)hb[3] << 16));
    }
}

// ============================ fp16 mma.sync GEMM ============================
// C[BM,BN] tile of A @ B^T.  A:[M,K] fp16 row-major, B:[N,K] fp16 row-major.
// 256 threads: 8 warps = 4 m-slices (32) x 2 n-slices (64). 2 CTAs/SM.
// MODE 0: outF = sigmoid(acc) fp32   (gate half of GEMM1 -> u)
// MODE 1: outF = acc fp32            (GEMM2 -> cand)
// MODE 2: outH = fp16(acc)           (value half of GEMM1 -> vx)
template <int MODE>
__global__ __launch_bounds__(NTHREADS, 2)
void gemm_mma(const __half* __restrict__ Ah, const __half* __restrict__ Bh,
              float* __restrict__ outF, __half* __restrict__ outH, int ntn)
{
    extern __shared__ char smem[];
    const uint32_t sb = smem_u32(smem);
    const int tid = threadIdx.x;
    const int wid = tid >> 5, lane = tid & 31;

    int per_group = GROUP_M * ntn;
    int group = blockIdx.x / per_group;
    int rem = blockIdx.x % per_group;
    const int bm = (group * GROUP_M + (rem % GROUP_M)) * BM;
    const int bn = (rem / GROUP_M) * BN;

    const int wm = wid & 3;   // 4 m-slices of 32
    const int wn = wid >> 2;  // 2 n-slices of 64

    uint32_t offA[2], offB[4];
#pragma unroll
    for (int mf = 0; mf < 2; mf++)
        offA[mf] = (uint32_t)(wm * 32 + mf * 16 + (lane & 15)) * ROWB + (lane >> 4) * 16;
#pragma unroll
    for (int p = 0; p < 4; p++)
        offB[p] = (uint32_t)(wn * 64 + p * 16 + ((lane >> 4) & 1) * 8 + (lane & 7)) * ROWB
                  + ((lane >> 3) & 1) * 16;

    float acc[2][8][4];
#pragma unroll
    for (int a = 0; a < 2; a++)
#pragma unroll
        for (int b = 0; b < 8; b++)
#pragma unroll
            for (int e = 0; e < 4; e++) acc[a][b][e] = 0.f;

    // per-stage: A 1024 + B 1024 16B-chunks -> 8 cp/thread in 2 halves
    auto load_half = [&](int kc, int half) {
        uint32_t base = sb + (uint32_t)(kc % NSTAGE) * STAGE_B;
        int k0 = kc * BK;
#pragma unroll
        for (int j = 0; j < 2; j++) {
            int ch = tid + (half * 2 + j) * NTHREADS;   // [0, 1024)
            int row = ch >> 3, kc8 = ch & 7;
            uint32_t doff = (uint32_t)row * ROWB + kc8 * 16;
            size_t ga = (size_t)(bm + row) * DD + k0 + kc8 * 8;
            cp16(base + A_OFF + doff, Ah + ga);
            size_t gb = (size_t)(bn + row) * DD + k0 + kc8 * 8;
            cp16(base + B_OFF + doff, Bh + gb);
        }
    };

    load_half(0, 0);
    load_half(0, 1);
    cp_commit();

    const int NKC = DD / BK;   // 16
    for (int kc = 0; kc < NKC; kc++) {
        cp_wait<0>();
        __syncthreads();

        uint32_t base = sb + (uint32_t)(kc % NSTAGE) * STAGE_B;
#pragma unroll
        for (int kk = 0; kk < 4; kk++) {
            uint32_t ah[2][4], bh[4][4];
#pragma unroll
            for (int mf = 0; mf < 2; mf++)
                ldsm4(ah[mf], base + A_OFF + offA[mf] + kk * 32);
#pragma unroll
            for (int p = 0; p < 4; p++)
                ldsm4(bh[p], base + B_OFF + offB[p] + kk * 32);
            if (kc + 1 < NKC) {
                if (kk == 0) load_half(kc + 1, 0);
                if (kk == 1) { load_half(kc + 1, 1); cp_commit(); }
            }
#pragma unroll
            for (int mf = 0; mf < 2; mf++) {
#pragma unroll
                for (int nf = 0; nf < 8; nf++) {
                    const uint32_t* b2 = &bh[nf >> 1][(nf & 1) * 2];
                    mma16816(acc[mf][nf], ah[mf], b2);
                }
            }
        }
    }

    // ---- epilogue ----
    const int r0 = bm + wm * 32 + (lane >> 2);
    const int c0 = bn + wn * 64 + (lane & 3) * 2;

#pragma unroll
    for (int mf = 0; mf < 2; mf++) {
        int r = r0 + mf * 16;
#pragma unroll
        for (int nf = 0; nf < 8; nf++) {
            int c = c0 + nf * 8;
            float* a = acc[mf][nf];
            if (MODE == 0) {
                float2 s0, s1;
                s0.x = 1.f / (1.f + __expf(-a[0]));
                s0.y = 1.f / (1.f + __expf(-a[1]));
                s1.x = 1.f / (1.f + __expf(-a[2]));
                s1.y = 1.f / (1.f + __expf(-a[3]));
                *(float2*)(outF + (size_t)r * DD + c)       = s0;
                *(float2*)(outF + (size_t)(r + 8) * DD + c) = s1;
            } else if (MODE == 1) {
                *(float2*)(outF + (size_t)r * DD + c)       = make_float2(a[0], a[1]);
                *(float2*)(outF + (size_t)(r + 8) * DD + c) = make_float2(a[2], a[3]);
            } else {
                __half2 h0 = __floats2half2_rn(a[0], a[1]);
                __half2 h1 = __floats2half2_rn(a[2], a[3]);
                *(__half2*)(outH + (size_t)r * DD + c)       = h0;
                *(__half2*)(outH + (size_t)(r + 8) * DD + c) = h1;
            }
        }
    }
}

// ============================ scan (diagonal recurrence) ============================
// h_t = u*h + (1-u)*c = fma(u, h-c, c). Reads g_u, g_c; writes y in-place into g_c.
__global__ __launch_bounds__(256) void scan_kernel()
{
    int idx = blockIdx.x * blockDim.x + threadIdx.x;   // 0 .. B*D-1
    int b = idx >> 10;
    int d = idx & (DD - 1);
    float* up = g_u + (size_t)b * TT * DD + d;
    float* cp = g_c + (size_t)b * TT * DD + d;
    float h = 0.f;
    for (int t = 0; t < TT; t += 16) {
        float uu[16], cc[16];
#pragma unroll
        for (int j = 0; j < 16; j++) {
            uu[j] = up[(size_t)(t + j) * DD];
            cc[j] = cp[(size_t)(t + j) * DD];
        }
#pragma unroll
        for (int j = 0; j < 16; j++) {
            h = fmaf(uu[j], h - cc[j], cc[j]);
            cc[j] = h;
        }
#pragma unroll
        for (int j = 0; j < 16; j++) cp[(size_t)(t + j) * DD] = cc[j];
    }
}

// ============================ LayerNorm ============================
__global__ __launch_bounds__(256) void ln_kernel(const float* __restrict__ gamma,
                                                 const float* __restrict__ beta,
                                                 float* __restrict__ out)
{
    int row = blockIdx.x;
    int t = threadIdx.x;
    const float4* yr = (const float4*)(g_c + (size_t)row * DD);
    float4 v = yr[t];
    float s = v.x + v.y + v.z + v.w;
    float q = v.x * v.x + v.y * v.y + v.z * v.z + v.w * v.w;

#pragma unroll
    for (int o = 16; o; o >>= 1) {
        s += __shfl_xor_sync(0xFFFFFFFFu, s, o);
        q += __shfl_xor_sync(0xFFFFFFFFu, q, o);
    }
    __shared__ float sw[8], qw[8];
    __shared__ float mu_s, inv_s;
    int w = t >> 5, l = t & 31;
    if (l == 0) { sw[w] = s; qw[w] = q; }
    __syncthreads();
    if (t == 0) {
        float S = 0.f, Q = 0.f;
#pragma unroll
        for (int i = 0; i < 8; i++) { S += sw[i]; Q += qw[i]; }
        float mu = S * (1.f / DD);
        float var = Q * (1.f / DD) - mu * mu;
        mu_s = mu;
        inv_s = rsqrtf(var + LN_EPS);
    }
    __syncthreads();
    float mu = mu_s, inv = inv_s;

    const float4* g4 = (const float4*)gamma;
    const float4* b4 = (const float4*)beta;
    float4 gv = g4[t], bv = b4[t];
    float4 o;
    o.x = (v.x - mu) * inv * gv.x + bv.x;
    o.y = (v.y - mu) * inv * gv.y + bv.y;
    o.z = (v.z - mu) * inv * gv.z + bv.z;
    o.w = (v.w - mu) * inv * gv.w + bv.w;
    ((float4*)(out + (size_t)row * DD))[t] = o;
}

// ============================ host ============================
extern "C" void kernel_launch(void* const* d_in, const int* in_sizes, int n_in,
                              void* d_out, int out_size)
{
    const float* x       = (const float*)d_in[0];
    const float* W_in    = (const float*)d_in[1];
    const float* W_state = (const float*)d_in[2];
    const float* gamma   = (const float*)d_in[3];
    const float* beta    = (const float*)d_in[4];
    float* out = (float*)d_out;

    void *pxh, *pwh, *psh, *pvh, *pu, *pc;
    cudaGetSymbolAddress(&pxh, g_xh);
    cudaGetSymbolAddress(&pwh, g_wh);  cudaGetSymbolAddress(&psh, g_sh);
    cudaGetSymbolAddress(&pvh, g_vh);
    cudaGetSymbolAddress(&pu,  g_u);   cudaGetSymbolAddress(&pc,  g_c);

    cudaFuncSetAttribute((const void*)gemm_mma<0>, cudaFuncAttributeMaxDynamicSharedMemorySize, SMEM_TOTAL);
    cudaFuncSetAttribute((const void*)gemm_mma<1>, cudaFuncAttributeMaxDynamicSharedMemorySize, SMEM_TOTAL);
    cudaFuncSetAttribute((const void*)gemm_mma<2>, cudaFuncAttributeMaxDynamicSharedMemorySize, SMEM_TOTAL);

    // conversions (all single fp16)
    { int n = MROWS * DD;  conv_kernel<<<(n / 4 + 255) / 256, 256>>>(x, (__half*)pxh, n); }
    { int n = 2 * DD * DD; conv_kernel<<<(n / 4 + 255) / 256, 256>>>(W_in, (__half*)pwh, n); }
    { int n = DD * DD;     conv_kernel<<<(n / 4 + 255) / 256, 256>>>(W_state, (__half*)psh, n); }

    const int ntm = MROWS / BM;        // 256
    const int ntn = DD / BN;           // 8

    // GEMM1 gate half: x @ W_in[0:D]^T -> u = sigmoid (fp32)
    gemm_mma<0><<<ntm * ntn, NTHREADS, SMEM_TOTAL>>>(
        (const __half*)pxh, (const __half*)pwh, (float*)pu, nullptr, ntn);

    // GEMM1 value half: x @ W_in[D:2D]^T -> vx fp16
    gemm_mma<2><<<ntm * ntn, NTHREADS, SMEM_TOTAL>>>(
        (const __half*)pxh, (const __half*)pwh + (size_t)DD * DD, nullptr, (__half*)pvh, ntn);

    // GEMM2: vx @ W_state^T -> cand fp32
    gemm_mma<1><<<ntm * ntn, NTHREADS, SMEM_TOTAL>>>(
        (const __half*)pvh, (const __half*)psh, (float*)pc, nullptr, ntn);

    // scan over T (y written in-place into g_c), then LN
    scan_kernel<<<(BB * DD) / 256, 256>>>();
    ln_kernel<<<MROWS, 256>>>(gamma, beta, out);
}

// round 14
// speedup vs baseline: 1.5348x; 1.2753x over previous
#include <cuda_runtime.h>
#include <cuda_fp16.h>
#include <math.h>
#include <stdint.h>

#define BB 16
#define TT 2048
#define DD 1024
#define MROWS (BB * TT)       // 32768
#define LN_EPS 1e-5f

// ---- GEMM tiling (proven shape) ----
#define BM 128
#define BN 128
#define BK 64                  // fp16 elems per k-chunk (4 kk-steps of 16)
#define NSTAGE 2
#define NTHREADS 256
#define ROWB 144               // 128B data + 16B pad (conflict-free ldmatrix)
#define A_OFF 0
#define B_OFF (BM * ROWB)                        // 18432
#define STAGE_B  (BM * ROWB + BN * ROWB)         // 36864
#define SMEM_TOTAL (NSTAGE * STAGE_B)            // 73728 -> 2 CTAs/SM

// ---- scratch (__device__ globals; no cudaMalloc allowed) ----
__device__ __half g_xh  [(size_t)MROWS * DD];    // x fp16
__device__ __half g_big [(size_t)2 * DD * DD];   // [W_gate ; W_fused] fp16
__device__ __half g_sh  [(size_t)DD * DD];       // W_state fp16
__device__ __half g_wvt [(size_t)DD * DD];       // W_value^T fp16  (wvt[k,d] = Wv[d,k])
__device__ float g_u[(size_t)MROWS * DD];        // u fp32
__device__ float g_c[(size_t)MROWS * DD];        // cand fp32; scan writes y in place

// ============================ device helpers ============================
__device__ __forceinline__ uint32_t smem_u32(const void* p) {
    uint32_t a;
    asm("{ .reg .u64 t; cvta.to.shared.u64 t, %1; cvt.u32.u64 %0, t; }" : "=r"(a) : "l"(p));
    return a;
}
__device__ __forceinline__ void cp16(uint32_t dst, const void* src) {
    asm volatile("cp.async.cg.shared.global [%0], [%1], 16;" :: "r"(dst), "l"(src));
}
__device__ __forceinline__ void cp_commit() {
    asm volatile("cp.async.commit_group;" ::: "memory");
}
template <int N>
__device__ __forceinline__ void cp_wait() {
    asm volatile("cp.async.wait_group %0;" :: "n"(N) : "memory");
}
__device__ __forceinline__ void ldsm4(uint32_t* r, uint32_t a) {
    asm volatile("ldmatrix.sync.aligned.m8n8.x4.shared.b16 {%0,%1,%2,%3}, [%4];"
                 : "=r"(r[0]), "=r"(r[1]), "=r"(r[2]), "=r"(r[3]) : "r"(a));
}
__device__ __forceinline__ void mma16816(float* c, const uint32_t* a, const uint32_t* b) {
    asm volatile(
        "mma.sync.aligned.m16n8k16.row.col.f32.f16.f16.f32 "
        "{%0,%1,%2,%3},{%4,%5,%6,%7},{%8,%9},{%0,%1,%2,%3};"
        : "+f"(c[0]), "+f"(c[1]), "+f"(c[2]), "+f"(c[3])
        : "r"(a[0]), "r"(a[1]), "r"(a[2]), "r"(a[3]), "r"(b[0]), "r"(b[1]));
}

// ============================ conversions ============================
// fp32 -> fp16
__global__ __launch_bounds__(256) void conv_kernel(
    const float* __restrict__ src, __half* __restrict__ dst, int n)
{
    int i = (blockIdx.x * blockDim.x + threadIdx.x) * 4;
    if (i < n) {
        float4 v = *(const float4*)(src + i);
        unsigned short hb[4];
        hb[0] = __half_as_ushort(__float2half_rn(v.x));
        hb[1] = __half_as_ushort(__float2half_rn(v.y));
        hb[2] = __half_as_ushort(__float2half_rn(v.z));
        hb[3] = __half_as_ushort(__float2half_rn(v.w));
        *(uint2*)(dst + i) = make_uint2((uint32_t)hb[0] | ((uint32_t)hb[1] << 16),
                                        (uint32_t)hb[2] | ((uint32_t)hb[3] << 16));
    }
}

// fp32 -> fp16, transposed: dst[k*DD + d] = src[d*DD + k]  (src = W_value, DD x DD)
__global__ __launch_bounds__(256) void transpose_conv_kernel(
    const float* __restrict__ src, __half* __restrict__ dst)
{
    __shared__ __half tile[32][33];
    int k0 = blockIdx.x * 32;   // output row block
    int d0 = blockIdx.y * 32;   // output col block
    int tx = threadIdx.x & 31;
    int ty = threadIdx.x >> 5;  // 0..7
#pragma unroll
    for (int j = 0; j < 4; j++) {
        int d = d0 + ty + j * 8;
        tile[ty + j * 8][tx] = __float2half_rn(src[(size_t)d * DD + k0 + tx]);
    }
    __syncthreads();
#pragma unroll
    for (int j = 0; j < 4; j++) {
        int k = k0 + ty + j * 8;
        dst[(size_t)k * DD + d0 + tx] = tile[tx][ty + j * 8];
    }
}

// ============================ fp16 mma.sync GEMM ============================
// C[BM,BN] tile of A @ B^T.  A:[M,K] fp16 row-major, B:[N,K] fp16 row-major. K=DD.
// 256 threads: 8 warps = 4 m-slices (32) x 2 n-slices (64). 2 CTAs/SM.
// MODE 0 (combined GEMM1): bn<DD: outF = sigmoid(acc) (u);
//                          bn>=DD: outF2 = acc (cand), col c-DD.
// MODE 2: outH = fp16(acc)  (W_fused = W_state @ W_value)
template <int MODE>
__global__ __launch_bounds__(NTHREADS, 2)
void gemm_mma(const __half* __restrict__ Ah, const __half* __restrict__ Bh,
              float* __restrict__ outF, float* __restrict__ outF2,
              __half* __restrict__ outH, int ntn, int gm)
{
    extern __shared__ char smem[];
    const uint32_t sb = smem_u32(smem);
    const int tid = threadIdx.x;
    const int wid = tid >> 5, lane = tid & 31;

    int per_group = gm * ntn;
    int group = blockIdx.x / per_group;
    int rem = blockIdx.x % per_group;
    const int bm = (group * gm + (rem % gm)) * BM;
    const int bn = (rem / gm) * BN;

    const int wm = wid & 3;   // 4 m-slices of 32
    const int wn = wid >> 2;  // 2 n-slices of 64

    uint32_t offA[2], offB[4];
#pragma unroll
    for (int mf = 0; mf < 2; mf++)
        offA[mf] = (uint32_t)(wm * 32 + mf * 16 + (lane & 15)) * ROWB + (lane >> 4) * 16;
#pragma unroll
    for (int p = 0; p < 4; p++)
        offB[p] = (uint32_t)(wn * 64 + p * 16 + ((lane >> 4) & 1) * 8 + (lane & 7)) * ROWB
                  + ((lane >> 3) & 1) * 16;

    float acc[2][8][4];
#pragma unroll
    for (int a = 0; a < 2; a++)
#pragma unroll
        for (int b = 0; b < 8; b++)
#pragma unroll
            for (int e = 0; e < 4; e++) acc[a][b][e] = 0.f;

    auto load_half = [&](int kc, int half) {
        uint32_t base = sb + (uint32_t)(kc % NSTAGE) * STAGE_B;
        int k0 = kc * BK;
#pragma unroll
        for (int j = 0; j < 2; j++) {
            int ch = tid + (half * 2 + j) * NTHREADS;   // [0, 1024)
            int row = ch >> 3, kc8 = ch & 7;
            uint32_t doff = (uint32_t)row * ROWB + kc8 * 16;
            size_t ga = (size_t)(bm + row) * DD + k0 + kc8 * 8;
            cp16(base + A_OFF + doff, Ah + ga);
            size_t gb = (size_t)(bn + row) * DD + k0 + kc8 * 8;
            cp16(base + B_OFF + doff, Bh + gb);
        }
    };

    load_half(0, 0);
    load_half(0, 1);
    cp_commit();

    const int NKC = DD / BK;   // 16
    for (int kc = 0; kc < NKC; kc++) {
        cp_wait<0>();
        __syncthreads();

        uint32_t base = sb + (uint32_t)(kc % NSTAGE) * STAGE_B;
#pragma unroll
        for (int kk = 0; kk < 4; kk++) {
            uint32_t ah[2][4], bh[4][4];
#pragma unroll
            for (int mf = 0; mf < 2; mf++)
                ldsm4(ah[mf], base + A_OFF + offA[mf] + kk * 32);
#pragma unroll
            for (int p = 0; p < 4; p++)
                ldsm4(bh[p], base + B_OFF + offB[p] + kk * 32);
            if (kc + 1 < NKC) {
                if (kk == 0) load_half(kc + 1, 0);
                if (kk == 1) { load_half(kc + 1, 1); cp_commit(); }
            }
#pragma unroll
            for (int mf = 0; mf < 2; mf++) {
#pragma unroll
                for (int nf = 0; nf < 8; nf++) {
                    const uint32_t* b2 = &bh[nf >> 1][(nf & 1) * 2];
                    mma16816(acc[mf][nf], ah[mf], b2);
                }
            }
        }
    }

    // ---- epilogue ----
    const int r0 = bm + wm * 32 + (lane >> 2);
    const int c0 = bn + wn * 64 + (lane & 3) * 2;
    const bool gate = (MODE == 0) && (bn < DD);

#pragma unroll
    for (int mf = 0; mf < 2; mf++) {
        int r = r0 + mf * 16;
#pragma unroll
        for (int nf = 0; nf < 8; nf++) {
            int c = c0 + nf * 8;
            float* a = acc[mf][nf];
            if (MODE == 0) {
                if (gate) {
                    float2 s0, s1;
                    s0.x = 1.f / (1.f + __expf(-a[0]));
                    s0.y = 1.f / (1.f + __expf(-a[1]));
                    s1.x = 1.f / (1.f + __expf(-a[2]));
                    s1.y = 1.f / (1.f + __expf(-a[3]));
                    *(float2*)(outF + (size_t)r * DD + c)       = s0;
                    *(float2*)(outF + (size_t)(r + 8) * DD + c) = s1;
                } else {
                    int cc = c - DD;
                    *(float2*)(outF2 + (size_t)r * DD + cc)       = make_float2(a[0], a[1]);
                    *(float2*)(outF2 + (size_t)(r + 8) * DD + cc) = make_float2(a[2], a[3]);
                }
            } else {
                __half2 h0 = __floats2half2_rn(a[0], a[1]);
                __half2 h1 = __floats2half2_rn(a[2], a[3]);
                *(__half2*)(outH + (size_t)r * DD + c)       = h0;
                *(__half2*)(outH + (size_t)(r + 8) * DD + c) = h1;
            }
        }
    }
}

// ============================ scan (diagonal recurrence) ============================
// h_t = u*h + (1-u)*c = fma(u, h-c, c). Reads g_u, g_c; writes y in-place into g_c.
__global__ __launch_bounds__(256) void scan_kernel()
{
    int idx = blockIdx.x * blockDim.x + threadIdx.x;   // 0 .. B*D-1
    int b = idx >> 10;
    int d = idx & (DD - 1);
    float* up = g_u + (size_t)b * TT * DD + d;
    float* cp = g_c + (size_t)b * TT * DD + d;
    float h = 0.f;
    for (int t = 0; t < TT; t += 16) {
        float uu[16], cc[16];
#pragma unroll
        for (int j = 0; j < 16; j++) {
            uu[j] = up[(size_t)(t + j) * DD];
            cc[j] = cp[(size_t)(t + j) * DD];
        }
#pragma unroll
        for (int j = 0; j < 16; j++) {
            h = fmaf(uu[j], h - cc[j], cc[j]);
            cc[j] = h;
        }
#pragma unroll
        for (int j = 0; j < 16; j++) cp[(size_t)(t + j) * DD] = cc[j];
    }
}

// ============================ LayerNorm ============================
__global__ __launch_bounds__(256) void ln_kernel(const float* __restrict__ gamma,
                                                 const float* __restrict__ beta,
                                                 float* __restrict__ out)
{
    int row = blockIdx.x;
    int t = threadIdx.x;
    const float4* yr = (const float4*)(g_c + (size_t)row * DD);
    float4 v = yr[t];
    float s = v.x + v.y + v.z + v.w;
    float q = v.x * v.x + v.y * v.y + v.z * v.z + v.w * v.w;

#pragma unroll
    for (int o = 16; o; o >>= 1) {
        s += __shfl_xor_sync(0xFFFFFFFFu, s, o);
        q += __shfl_xor_sync(0xFFFFFFFFu, q, o);
    }
    __shared__ float sw[8], qw[8];
    __shared__ float mu_s, inv_s;
    int w = t >> 5, l = t & 31;
    if (l == 0) { sw[w] = s; qw[w] = q; }
    __syncthreads();
    if (t == 0) {
        float S = 0.f, Q = 0.f;
#pragma unroll
        for (int i = 0; i < 8; i++) { S += sw[i]; Q += qw[i]; }
        float mu = S * (1.f / DD);
        float var = Q * (1.f / DD) - mu * mu;
        mu_s = mu;
        inv_s = rsqrtf(var + LN_EPS);
    }
    __syncthreads();
    float mu = mu_s, inv = inv_s;

    const float4* g4 = (const float4*)gamma;
    const float4* b4 = (const float4*)beta;
    float4 gv = g4[t], bv = b4[t];
    float4 o;
    o.x = (v.x - mu) * inv * gv.x + bv.x;
    o.y = (v.y - mu) * inv * gv.y + bv.y;
    o.z = (v.z - mu) * inv * gv.z + bv.z;
    o.w = (v.w - mu) * inv * gv.w + bv.w;
    ((float4*)(out + (size_t)row * DD))[t] = o;
}

// ============================ host ============================
extern "C" void kernel_launch(void* const* d_in, const int* in_sizes, int n_in,
                              void* d_out, int out_size)
{
    const float* x       = (const float*)d_in[0];
    const float* W_in    = (const float*)d_in[1];
    const float* W_state = (const float*)d_in[2];
    const float* gamma   = (const float*)d_in[3];
    const float* beta    = (const float*)d_in[4];
    float* out = (float*)d_out;

    void *pxh, *pbig, *psh, *pwvt, *pu, *pc;
    cudaGetSymbolAddress(&pxh, g_xh);
    cudaGetSymbolAddress(&pbig, g_big);
    cudaGetSymbolAddress(&psh, g_sh);
    cudaGetSymbolAddress(&pwvt, g_wvt);
    cudaGetSymbolAddress(&pu,  g_u);
    cudaGetSymbolAddress(&pc,  g_c);

    cudaFuncSetAttribute((const void*)gemm_mma<0>, cudaFuncAttributeMaxDynamicSharedMemorySize, SMEM_TOTAL);
    cudaFuncSetAttribute((const void*)gemm_mma<2>, cudaFuncAttributeMaxDynamicSharedMemorySize, SMEM_TOTAL);

    // conversions: x -> fp16; W_in gate half -> g_big[0:D*D]; W_state -> g_sh;
    // W_in value half -> transposed fp16 g_wvt
    { int n = MROWS * DD;  conv_kernel<<<(n / 4 + 255) / 256, 256>>>(x, (__half*)pxh, n); }
    { int n = DD * DD;     conv_kernel<<<(n / 4 + 255) / 256, 256>>>(W_in, (__half*)pbig, n); }
    { int n = DD * DD;     conv_kernel<<<(n / 4 + 255) / 256, 256>>>(W_state, (__half*)psh, n); }
    {
        dim3 g(DD / 32, DD / 32);
        transpose_conv_kernel<<<g, 256>>>(W_in + (size_t)DD * DD, (__half*)pwvt);
    }

    // W_fused = W_state @ W_value  -> g_big[D*D : 2*D*D]  (fp16 out)
    // C[e,k] = sum_d Ws[e,d] * WvT[k,d];  M=N=K=DD. grid 64, gm=8.
    gemm_mma<2><<<(DD / BM) * (DD / BN), NTHREADS, SMEM_TOTAL>>>(
        (const __half*)psh, (const __half*)pwvt,
        nullptr, nullptr, (__half*)pbig + (size_t)DD * DD, DD / BN, 8);

    // Combined GEMM1: x @ [W_gate ; W_fused]^T -> u (sigmoid) + cand (fp32)
    {
        int ntm = MROWS / BM, ntn = 2 * DD / BN;   // 256, 16
        gemm_mma<0><<<ntm * ntn, NTHREADS, SMEM_TOTAL>>>(
            (const __half*)pxh, (const __half*)pbig,
            (float*)pu, (float*)pc, nullptr, ntn, 16);
    }

    // scan over T (y written in-place into g_c), then LN
    scan_kernel<<<(BB * DD) / 256, 256>>>();
    ln_kernel<<<MROWS, 256>>>(gamma, beta, out);
}